// round 17
// baseline (speedup 1.0000x reference)
#include <cuda_runtime.h>
#include <cuda_bf16.h>
#include <math.h>
#include <stdint.h>

#define N_TOT 512
#define D_DIM 512

__device__ __align__(16) float g_LO[N_TOT * N_TOT];   // lo = -dist/2
__device__ __align__(16) float g_ys[N_TOT];
__device__ __align__(16) int   g_perm[N_TOT];
__device__ unsigned g_ccnt;                            // monotonic grid barrier
__device__ double g_acc;
__device__ int    g_count;

__device__ __forceinline__ const float* frow(const float* wt, const float* mt, int r) {
    return (r < 256) ? (wt + r * D_DIM) : (mt + (r - 256) * D_DIM);
}
__device__ __forceinline__ float lab(const float* lw, const float* lm, int r) {
    return (r < 256) ? lw[r] : lm[r - 256];
}

__device__ __forceinline__ uint32_t smem_u32(const void* p) {
    uint32_t a;
    asm("{ .reg .u64 t; cvta.to.shared.u64 t, %1; cvt.u32.u64 %0, t; }" : "=r"(a) : "l"(p));
    return a;
}
__device__ __forceinline__ void ldsm4(uint32_t* r, uint32_t addr) {
    asm volatile("ldmatrix.sync.aligned.m8n8.x4.shared.b16 {%0,%1,%2,%3}, [%4];"
                 : "=r"(r[0]), "=r"(r[1]), "=r"(r[2]), "=r"(r[3]) : "r"(addr));
}
__device__ __forceinline__ void mma_bf16(float* c, const uint32_t* a, const uint32_t* b) {
    asm volatile("mma.sync.aligned.m16n8k16.row.col.f32.bf16.bf16.f32 "
                 "{%0,%1,%2,%3}, {%4,%5,%6,%7}, {%8,%9}, {%0,%1,%2,%3};"
                 : "+f"(c[0]), "+f"(c[1]), "+f"(c[2]), "+f"(c[3])
                 : "r"(a[0]), "r"(a[1]), "r"(a[2]), "r"(a[3]), "r"(b[0]), "r"(b[1]));
}
__device__ __forceinline__ void split4(float4 f, uint2& h, uint2& l) {
    __nv_bfloat162 h0 = __floats2bfloat162_rn(f.x, f.y);
    __nv_bfloat162 h1 = __floats2bfloat162_rn(f.z, f.w);
    float2 g0 = __bfloat1622float2(h0), g1 = __bfloat1622float2(h1);
    __nv_bfloat162 l0 = __floats2bfloat162_rn(f.x - g0.x, f.y - g0.y);
    __nv_bfloat162 l1 = __floats2bfloat162_rn(f.z - g1.x, f.w - g1.y);
    h = make_uint2(*(uint32_t*)&h0, *(uint32_t*)&h1);
    l = make_uint2(*(uint32_t*)&l0, *(uint32_t*)&l1);
}

#define STRIDE 40
#define BK 32
#define NCHUNK 16
#define NBUF 3
#define GRID_F 148
#define NTB 68                    // gemm blocks, 2 tiles each = 136 tiles

// per-tile smem: nA(128B) nB(128B) buf[4][3][2560B] = 256 + 30720 = 30976 -> pitch 31232
#define TILE_PITCH 31232
#define BUF_ARR_B 7680
#define BUF_STEP_B 2560
#define SMEM_BYTES 65536

__global__ void __launch_bounds__(512, 1)
fused_kernel(const float* __restrict__ wt, const float* __restrict__ mt,
             const float* __restrict__ lw, const float* __restrict__ lm,
             float* __restrict__ out) {
    extern __shared__ char dsm[];
    const int t = threadIdx.x;
    const int bid = blockIdx.x;

    // ===================== Phase 1 =====================
    if (bid < NTB) {
        const int h = t >> 8;          // half-block: one tile each
        const int t2 = t & 255;
        const int w = t2 >> 5, lane = t2 & 31;
        const int tile = bid * 2 + h;

        int ti = 0, base = 0;
        while (base + (16 - ti) <= tile) { base += 16 - ti; ti++; }
        const int tj = ti + (tile - base);
        const int I = ti * 32, J = tj * 32;

        char* tb = dsm + h * TILE_PITCH;
        float* nA = (float*)tb;
        float* nB = (float*)(tb + 128);
        unsigned short* bufb = (unsigned short*)(tb + 256);
        float (*stage)[33] = (float(*)[33])(tb + 256);

        const int g = t2 >> 3, q = t2 & 7;
        const float* arp = frow(wt, mt, I + g) + q * 4;
        const float* brp = frow(wt, mt, J + g) + q * 4;
        float na = 0.f, nb = 0.f;
        const uint32_t se = g * STRIDE + q * 4;

        const int wm = w >> 2, wn = w & 3;
        float c[4] = {};

        const uint32_t a_hi_b = smem_u32(bufb);
        const uint32_t a_lo_b = a_hi_b + BUF_ARR_B;
        const uint32_t b_hi_b = a_hi_b + 2 * BUF_ARR_B;
        const uint32_t b_lo_b = a_hi_b + 3 * BUF_ARR_B;

        const uint32_t a_off = (uint32_t)((wm * 16 + (lane & 15)) * (STRIDE * 2) + ((lane >> 4) & 1) * 16);
        const uint32_t b_off = (uint32_t)((wn * 8 + (lane & 7)) * (STRIDE * 2) + (lane >> 3) * 16);

        unsigned short* A_HI = bufb;
        unsigned short* A_LO = bufb + BUF_ARR_B / 2;
        unsigned short* B_HI = bufb + BUF_ARR_B;
        unsigned short* B_LO = bufb + 3 * BUF_ARR_B / 2;
        const int bstep_e = BUF_STEP_B / 2;   // ushort elems per buffer

        float4 Ra, Rb;
        Ra = *(const float4*)arp; Rb = *(const float4*)brp;
        {
            uint2 hh, ll;
            na += Ra.x*Ra.x + Ra.y*Ra.y + Ra.z*Ra.z + Ra.w*Ra.w;
            split4(Ra, hh, ll);
            *(uint2*)&A_HI[se] = hh; *(uint2*)&A_LO[se] = ll;
            nb += Rb.x*Rb.x + Rb.y*Rb.y + Rb.z*Rb.z + Rb.w*Rb.w;
            split4(Rb, hh, ll);
            *(uint2*)&B_HI[se] = hh; *(uint2*)&B_LO[se] = ll;
        }
        Ra = *(const float4*)(arp + BK); Rb = *(const float4*)(brp + BK);

        for (int n = 0; n < NCHUNK; n++) {
            const int cur = n % NBUF;
            if (n + 1 < NCHUNK) {
                const int nxt = (n + 1) % NBUF;
                uint2 hh, ll;
                na += Ra.x*Ra.x + Ra.y*Ra.y + Ra.z*Ra.z + Ra.w*Ra.w;
                split4(Ra, hh, ll);
                *(uint2*)&A_HI[nxt * bstep_e + se] = hh; *(uint2*)&A_LO[nxt * bstep_e + se] = ll;
                nb += Rb.x*Rb.x + Rb.y*Rb.y + Rb.z*Rb.z + Rb.w*Rb.w;
                split4(Rb, hh, ll);
                *(uint2*)&B_HI[nxt * bstep_e + se] = hh; *(uint2*)&B_LO[nxt * bstep_e + se] = ll;
            }
            if (n + 2 < NCHUNK) {
                const int ko = (n + 2) * BK;
                Ra = *(const float4*)(arp + ko);
                Rb = *(const float4*)(brp + ko);
            }
            __syncthreads();

            uint32_t Bh[4], Bl[4];
            ldsm4(Bh, b_hi_b + cur * BUF_STEP_B + b_off);
            ldsm4(Bl, b_lo_b + cur * BUF_STEP_B + b_off);
            #pragma unroll
            for (int ks = 0; ks < 2; ks++) {
                uint32_t Ah[4], Al[4];
                ldsm4(Ah, a_hi_b + cur * BUF_STEP_B + a_off + ks * 32);
                ldsm4(Al, a_lo_b + cur * BUF_STEP_B + a_off + ks * 32);
                mma_bf16(c, Ah, Bh + ks * 2);
                mma_bf16(c, Ah, Bl + ks * 2);
                mma_bf16(c, Al, Bh + ks * 2);
            }
        }

        na += __shfl_xor_sync(0xffffffffu, na, 1);
        na += __shfl_xor_sync(0xffffffffu, na, 2);
        na += __shfl_xor_sync(0xffffffffu, na, 4);
        nb += __shfl_xor_sync(0xffffffffu, nb, 1);
        nb += __shfl_xor_sync(0xffffffffu, nb, 2);
        nb += __shfl_xor_sync(0xffffffffu, nb, 4);
        __syncthreads();
        if (q == 0) { nA[g] = na; nB[g] = nb; }
        __syncthreads();

        const int r0 = wm * 16 + (lane >> 2);
        const int cL = wn * 8 + (lane & 3) * 2;
        const float ni0 = nA[r0], ni1 = nA[r0 + 8];
        const float nj0 = nB[cL], nj1 = nB[cL + 1];
        float sq, v00, v01, v10, v11;
        sq = fmaf(-2.f, c[0], ni0 + nj0); v00 = -0.5f * sqrtf(fmaxf(sq, 0.f));
        sq = fmaf(-2.f, c[1], ni0 + nj1); v01 = -0.5f * sqrtf(fmaxf(sq, 0.f));
        sq = fmaf(-2.f, c[2], ni1 + nj0); v10 = -0.5f * sqrtf(fmaxf(sq, 0.f));
        sq = fmaf(-2.f, c[3], ni1 + nj1); v11 = -0.5f * sqrtf(fmaxf(sq, 0.f));
        *(float2*)&g_LO[(I + r0) * N_TOT + J + cL]     = make_float2(v00, v01);
        *(float2*)&g_LO[(I + r0 + 8) * N_TOT + J + cL] = make_float2(v10, v11);

        // mirror: unconditional barriers (halves may differ in ti==tj)
        stage[r0][cL] = v00;     stage[r0][cL + 1] = v01;
        stage[r0 + 8][cL] = v10; stage[r0 + 8][cL + 1] = v11;
        __syncthreads();
        if (ti != tj) {
            const int mc = t2 >> 3;
            const int rg = (t2 & 7) * 4;
            float4 o;
            o.x = stage[rg + 0][mc]; o.y = stage[rg + 1][mc];
            o.z = stage[rg + 2][mc]; o.w = stage[rg + 3][mc];
            *(float4*)&g_LO[(J + mc) * N_TOT + I + rg] = o;
        }
    } else if (bid == NTB) {
        // ---- sort block: 512 threads, 1 element each; resets accumulators ----
        if (t == 0) { g_acc = 0.0; g_count = 0; }
        float* ls = (float*)dsm;
        ls[t] = lab(lw, lm, t);
        __syncthreads();
        const float ye = ls[t];
        int rank = 0;
        const float4* L4 = (const float4*)ls;
        #pragma unroll 8
        for (int j4 = 0; j4 < N_TOT / 4; j4++) {
            float4 v = L4[j4];
            int j = j4 * 4;
            rank += (v.x < ye) || (v.x == ye && (j + 0) < t);
            rank += (v.y < ye) || (v.y == ye && (j + 1) < t);
            rank += (v.z < ye) || (v.z == ye && (j + 2) < t);
            rank += (v.w < ye) || (v.w == ye && (j + 3) < t);
        }
        g_ys[rank] = ye;
        g_perm[rank] = t;
    }

    // ===================== grid barrier (monotonic, replay-safe) =====================
    __syncthreads();
    if (t == 0) {
        __threadfence();
        unsigned ticket = atomicAdd(&g_ccnt, 1u);
        unsigned target = (ticket / (unsigned)GRID_F + 1u) * (unsigned)GRID_F;
        while (atomicAdd(&g_ccnt, 0u) < target) {}
        __threadfence();
    }
    __syncthreads();

    // ===================== Phase 2: loss rows (verbatim round-8 body) ========
    float* sLO   = (float*)dsm;
    float* sY    = (float*)(dsm + 2048);
    float* sD    = (float*)(dsm + 4096);
    float* sP    = (float*)(dsm + 6144);          // 513 floats
    float* warpS = (float*)(dsm + 8208);          // 16 floats
    int*   sint  = (int*)(dsm + 8272);            // [0]=sp, [1]=spos

    const int m = t;
    const int lane = m & 31, w = m >> 5;

    for (int i = (GRID_F - 1 - bid); i < N_TOT; i += GRID_F) {
        __syncthreads();   // protect smem reuse across iterations / after phase 1

        sLO[m] = g_LO[i * N_TOT + m];
        sY[m]  = g_ys[m];
        const int pm = g_perm[m];
        const float yi = lab(lw, lm, i);
        if (pm == i) sint[1] = m;
        __syncthreads();

        const float tm = fabsf(yi - sY[m]);
        sD[m] = tm;
        if (m == 0) {
            int lo_ = 0, hi_ = N_TOT;
            while (lo_ < hi_) { int mid = (lo_ + hi_) >> 1; if (sY[mid] >= yi) hi_ = mid; else lo_ = mid + 1; }
            sint[0] = lo_;
        }

        const float lo_s = sLO[pm];
        const float e = (pm == i) ? 0.f : __expf(lo_s);

        float v = e;
        #pragma unroll
        for (int o = 1; o < 32; o <<= 1) {
            float nvl = __shfl_up_sync(0xffffffffu, v, o);
            if (lane >= o) v += nvl;
        }
        if (lane == 31) warpS[w] = v;
        __syncthreads();
        if (w == 0) {
            float s = (lane < 16) ? warpS[lane] : 0.f;
            #pragma unroll
            for (int o = 1; o < 16; o <<= 1) {
                float nvl = __shfl_up_sync(0xffffffffu, s, o);
                if (lane >= o) s += nvl;
            }
            if (lane < 16) warpS[lane] = s;
        }
        __syncthreads();
        const float off = (w > 0) ? warpS[w - 1] : 0.f;
        const float S = warpS[15];
        sP[m] = off + v - e;
        if (m == N_TOT - 1) sP[N_TOT] = off + v;
        __syncthreads();

        const int p = sint[0];
        const int spos = sint[1];
        int a, b;
        if (m < p) {
            int j = m + 1;
            while (j < p && sD[j] == tm) j++;
            a = j;
            int lo_ = p, hi_ = N_TOT;
            while (lo_ < hi_) { int mid = (lo_ + hi_) >> 1; if (sD[mid] >= tm) hi_ = mid; else lo_ = mid + 1; }
            b = lo_;
        } else {
            int j = m;
            while (j > p && sD[j - 1] == tm) j--;
            b = j;
            int lo_ = 0, hi_ = p;
            while (lo_ < hi_) { int mid = (lo_ + hi_) >> 1; if (sD[mid] < tm) hi_ = mid; else lo_ = mid + 1; }
            a = lo_;
        }

        const float denom = sP[a] + (S - sP[b]);
        float term = (m == spos) ? 0.f : (lo_s - __logf(denom));

        #pragma unroll
        for (int o = 16; o; o >>= 1) term += __shfl_xor_sync(0xffffffffu, term, o);
        __syncthreads();
        if (lane == 0) warpS[w] = term;
        __syncthreads();
        if (m == 0) {
            float s = 0.f;
            #pragma unroll
            for (int qq = 0; qq < 16; qq++) s += warpS[qq];
            atomicAdd(&g_acc, (double)s);
            __threadfence();
            int done = atomicAdd(&g_count, 1);
            if (done == N_TOT - 1) {
                double total = atomicAdd(&g_acc, 0.0);
                out[0] = (float)(-total / (double)(N_TOT * (N_TOT - 1)));
            }
        }
    }
}

extern "C" void kernel_launch(void* const* d_in, const int* in_sizes, int n_in,
                              void* d_out, int out_size) {
    const float* wt = (const float*)d_in[0];
    const float* mt = (const float*)d_in[1];
    const float* lw = (const float*)d_in[2];
    const float* lm = (const float*)d_in[3];
    float* out = (float*)d_out;

    static int attr_set = 0;
    if (!attr_set) {
        cudaFuncSetAttribute(fused_kernel,
                             cudaFuncAttributeMaxDynamicSharedMemorySize, SMEM_BYTES);
        attr_set = 1;
    }

    fused_kernel<<<GRID_F, 512, SMEM_BYTES>>>(wt, mt, lw, lm, out);
}